// round 3
// baseline (speedup 1.0000x reference)
#include <cuda_runtime.h>
#include <math.h>

// ---------------------------------------------------------------------------
// DenseGCN3Layer on GB300.
// Pipeline per launch:
//   zero deg -> histogram(dst) -> 1-block scan (row_start, cursor, dinv)
//   -> scatter edges to CSR (src id + dinv[src] weight)
//   -> GEMM A: x @ [W1|Ws02|Ws03]  (fp32x2 packed FMA)
//   -> AGG1 (warp/node, 64 feats) -> x1
//   -> GEMM B: x1 @ [W2|Ws13]
//   -> AGG2 (32 feats, + s02 skip) -> x2
//   -> GEMM C: x2 @ W3
//   -> AGG3 (16 feats, + s03 + s13 skips, fused Wout dot + sigmoid) -> out
// ---------------------------------------------------------------------------

#define MAXN 100000
#define MAXE 3200000

__device__ int   g_deg[MAXN];
__device__ int   g_row[MAXN + 1];
__device__ int   g_cur[MAXN];
__device__ float g_dinv[MAXN];
__device__ int   g_srcs[MAXE];
__device__ float g_wts[MAXE];

__device__ float g_h1[(size_t)MAXN * 64];
__device__ float g_s02[(size_t)MAXN * 32];
__device__ float g_s03[(size_t)MAXN * 16];
__device__ float g_x1[(size_t)MAXN * 64];
__device__ float g_h2[(size_t)MAXN * 32];
__device__ float g_s13[(size_t)MAXN * 16];
__device__ float g_x2[(size_t)MAXN * 32];
__device__ float g_h3[(size_t)MAXN * 16];

// ---------------------------------------------------------------------------
// helpers: packed f32x2 FMA (sm_103a)
// ---------------------------------------------------------------------------
__device__ __forceinline__ void ffma2(unsigned long long& acc,
                                      unsigned long long a,
                                      unsigned long long b) {
    asm("fma.rn.f32x2 %0, %1, %2, %0;" : "+l"(acc) : "l"(a), "l"(b));
}

__device__ __forceinline__ unsigned long long pack2(float x) {
    unsigned long long r;
    unsigned int u = __float_as_uint(x);
    asm("mov.b64 %0, {%1, %1};" : "=l"(r) : "r"(u));
    return r;
}

// ---------------------------------------------------------------------------
// graph structure build
// ---------------------------------------------------------------------------
__global__ void k_zero(int N) {
    int i = blockIdx.x * blockDim.x + threadIdx.x;
    if (i < N) g_deg[i] = 0;
}

__global__ void k_hist(const int* __restrict__ dst, int E) {
    int e = blockIdx.x * blockDim.x + threadIdx.x;
    if (e < E) atomicAdd(&g_deg[dst[e]], 1);
}

__global__ void k_scan(int N, int chunk) {
    __shared__ int sums[1024];
    int t = threadIdx.x;
    int beg = t * chunk;
    int end = beg + chunk; if (end > N) end = N;
    int s = 0;
    for (int i = beg; i < end; i++) s += g_deg[i];
    sums[t] = s;
    __syncthreads();
    for (int off = 1; off < 1024; off <<= 1) {
        int v = (t >= off) ? sums[t - off] : 0;
        __syncthreads();
        if (t >= off) sums[t] += v;
        __syncthreads();
    }
    int run = (t == 0) ? 0 : sums[t - 1];
    for (int i = beg; i < end; i++) {
        int d = g_deg[i];
        g_row[i] = run;
        g_cur[i] = run;
        g_dinv[i] = rsqrtf((float)d + 1.0f);
        run += d;
    }
    if (t == 1023) g_row[N] = sums[1023];
}

__global__ void k_scatter(const int* __restrict__ src,
                          const int* __restrict__ dst, int E) {
    int e = blockIdx.x * blockDim.x + threadIdx.x;
    if (e < E) {
        int d = dst[e];
        int s = src[e];
        int pos = atomicAdd(&g_cur[d], 1);
        g_srcs[pos] = s;
        g_wts[pos]  = g_dinv[s];
    }
}

// ---------------------------------------------------------------------------
// Fused GEMM: out = X[N,KD] @ [Wa | Wb | Wc]  (widths 16*J1, 16*(J2-J1), 16*(NJ-J2))
// BM=64 nodes per block, 256 threads, fp32x2 accumulation.
// Thread (tx,ty): cols {tx+16j}, nodes {ty*4 .. ty*4+3} packed in pairs.
// ---------------------------------------------------------------------------
template <int KD, int NJ, int J1, int J2>
__global__ __launch_bounds__(256) void k_gemm(
    const float* __restrict__ X, int N,
    const float* __restrict__ Wa,
    const float* __restrict__ Wb,
    const float* __restrict__ Wc,
    float* __restrict__ Oa, float* __restrict__ Ob, float* __restrict__ Oc) {
    constexpr int BM = 64, BK = 16, ND = NJ * 16;
    constexpr int C1 = J1 * 16, C2 = (J2 - J1) * 16, C3 = (NJ - J2) * 16;
    __shared__ __align__(16) float Xs[BK][BM];
    __shared__ float Ws[BK][ND];

    int tid = threadIdx.x;
    int tx = tid & 15, ty = tid >> 4;
    int g0 = blockIdx.x * BM;

    unsigned long long acc[2][NJ];
#pragma unroll
    for (int p = 0; p < 2; p++)
#pragma unroll
        for (int j = 0; j < NJ; j++) acc[p][j] = 0ull;

    int lr = tid >> 2;  // load row 0..63
    int lq = tid & 3;   // quad within 16 cols

    for (int kk = 0; kk < KD; kk += BK) {
        float4 xv = make_float4(0.f, 0.f, 0.f, 0.f);
        int gr = g0 + lr;
        if (gr < N)
            xv = *(const float4*)(X + (size_t)gr * KD + kk + lq * 4);
        Xs[lq * 4 + 0][lr] = xv.x;
        Xs[lq * 4 + 1][lr] = xv.y;
        Xs[lq * 4 + 2][lr] = xv.z;
        Xs[lq * 4 + 3][lr] = xv.w;

#pragma unroll
        for (int it = 0; it < (BK * ND) / 256; it++) {
            int idx = it * 256 + tid;
            int k = idx / ND, c = idx % ND;
            float v;
            if (c < C1)
                v = Wa[(size_t)(kk + k) * C1 + c];
            else if (C2 > 0 && c < C1 + C2)
                v = Wb[(size_t)(kk + k) * C2 + (c - C1)];
            else
                v = Wc[(size_t)(kk + k) * (C3 > 0 ? C3 : 1) + (c - C1 - C2)];
            Ws[k][c] = v;
        }
        __syncthreads();

#pragma unroll
        for (int k = 0; k < BK; k++) {
            ulonglong2 av = *(const ulonglong2*)&Xs[k][ty * 4];
#pragma unroll
            for (int j = 0; j < NJ; j++) {
                unsigned long long bb = pack2(Ws[k][tx + 16 * j]);
                ffma2(acc[0][j], av.x, bb);
                ffma2(acc[1][j], av.y, bb);
            }
        }
        __syncthreads();
    }

#pragma unroll
    for (int p = 0; p < 2; p++) {
#pragma unroll
        for (int u = 0; u < 2; u++) {
            int n = g0 + ty * 4 + p * 2 + u;
            if (n >= N) continue;
#pragma unroll
            for (int j = 0; j < NJ; j++) {
                unsigned int bits = (u == 0)
                    ? (unsigned int)(acc[p][j] & 0xffffffffull)
                    : (unsigned int)(acc[p][j] >> 32);
                float v = __uint_as_float(bits);
                int col = tx + 16 * j;
                if (j < J1)
                    Oa[(size_t)n * C1 + col] = v;
                else if (j < J2)
                    Ob[(size_t)n * (C2 > 0 ? C2 : 1) + col - C1] = v;
                else
                    Oc[(size_t)n * (C3 > 0 ? C3 : 1) + col - C1 - C2] = v;
            }
        }
    }
}

// ---------------------------------------------------------------------------
// Aggregations: one warp per destination node, CSR gather, no atomics.
// out[i] = relu( dinv[i]*(sum_e w_e*h[src_e] + dinv[i]*h[i]) + bias (+ skips) )
// ---------------------------------------------------------------------------
__global__ __launch_bounds__(256) void k_agg1(const float* __restrict__ b1, int N) {
    int w = (blockIdx.x * blockDim.x + threadIdx.x) >> 5;
    int lane = threadIdx.x & 31;
    if (w >= N) return;
    int rs = g_row[w], re = g_row[w + 1];
    float di = g_dinv[w];
    float ax = 0.f, ay = 0.f;
    for (int base = rs; base < re; base += 32) {
        int e = base + lane;
        int s = 0; float wt = 0.f;
        if (e < re) { s = g_srcs[e]; wt = g_wts[e]; }
        int cnt = re - base; if (cnt > 32) cnt = 32;
        for (int j = 0; j < cnt; j++) {
            int   ss = __shfl_sync(0xffffffffu, s, j);
            float ww = __shfl_sync(0xffffffffu, wt, j);
            float2 hv = *(const float2*)(g_h1 + (size_t)ss * 64 + lane * 2);
            ax = fmaf(ww, hv.x, ax);
            ay = fmaf(ww, hv.y, ay);
        }
    }
    float2 hs = *(const float2*)(g_h1 + (size_t)w * 64 + lane * 2);
    float rx = fmaf(di, fmaf(di, hs.x, ax), __ldg(b1 + lane * 2));
    float ry = fmaf(di, fmaf(di, hs.y, ay), __ldg(b1 + lane * 2 + 1));
    float2 o;
    o.x = fmaxf(rx, 0.f);
    o.y = fmaxf(ry, 0.f);
    *(float2*)(g_x1 + (size_t)w * 64 + lane * 2) = o;
}

__global__ __launch_bounds__(256) void k_agg2(const float* __restrict__ b2,
                                              const float* __restrict__ bs02, int N) {
    int w = (blockIdx.x * blockDim.x + threadIdx.x) >> 5;
    int lane = threadIdx.x & 31;
    if (w >= N) return;
    int rs = g_row[w], re = g_row[w + 1];
    float di = g_dinv[w];
    float acc = 0.f;
    for (int base = rs; base < re; base += 32) {
        int e = base + lane;
        int s = 0; float wt = 0.f;
        if (e < re) { s = g_srcs[e]; wt = g_wts[e]; }
        int cnt = re - base; if (cnt > 32) cnt = 32;
        for (int j = 0; j < cnt; j++) {
            int   ss = __shfl_sync(0xffffffffu, s, j);
            float ww = __shfl_sync(0xffffffffu, wt, j);
            acc = fmaf(ww, g_h2[(size_t)ss * 32 + lane], acc);
        }
    }
    float hs = g_h2[(size_t)w * 32 + lane];
    float r = fmaf(di, fmaf(di, hs, acc),
                   __ldg(b2 + lane) + g_s02[(size_t)w * 32 + lane] + __ldg(bs02 + lane));
    g_x2[(size_t)w * 32 + lane] = fmaxf(r, 0.f);
}

__global__ __launch_bounds__(256) void k_agg3(const float* __restrict__ b3,
                                              const float* __restrict__ bs03,
                                              const float* __restrict__ bs13,
                                              const float* __restrict__ Wout,
                                              const float* __restrict__ bout,
                                              float* __restrict__ out, int N) {
    int w = (blockIdx.x * blockDim.x + threadIdx.x) >> 5;
    int lane = threadIdx.x & 31;
    if (w >= N) return;
    int half = lane >> 4;
    int f = lane & 15;
    int rs = g_row[w], re = g_row[w + 1];
    float di = g_dinv[w];
    float acc = 0.f;
    for (int base = rs; base < re; base += 32) {
        int e = base + lane;
        int s = 0; float wt = 0.f;
        if (e < re) { s = g_srcs[e]; wt = g_wts[e]; }
        int cnt = re - base; if (cnt > 32) cnt = 32;
        // halves process even/odd edges; uniform trip count keeps shfls converged
        for (int jj = 0; jj < cnt; jj += 2) {
            int j = jj + half;
            int   ss = __shfl_sync(0xffffffffu, s, j & 31);
            float ww = __shfl_sync(0xffffffffu, wt, j & 31);
            if (j < cnt)
                acc = fmaf(ww, g_h3[(size_t)ss * 16 + f], acc);
        }
    }
    acc += __shfl_xor_sync(0xffffffffu, acc, 16);
    float hs = g_h3[(size_t)w * 16 + f];
    float extra = __ldg(b3 + f) + g_s03[(size_t)w * 16 + f] + __ldg(bs03 + f) +
                  g_s13[(size_t)w * 16 + f] + __ldg(bs13 + f);
    float t = fmaf(di, fmaf(di, hs, acc), extra);
    t = fmaxf(t, 0.f);
    float p = t * __ldg(Wout + f);
    p += __shfl_xor_sync(0xffffffffu, p, 8);
    p += __shfl_xor_sync(0xffffffffu, p, 4);
    p += __shfl_xor_sync(0xffffffffu, p, 2);
    p += __shfl_xor_sync(0xffffffffu, p, 1);
    if (lane == 0)
        out[w] = 1.0f / (1.0f + expf(-(p + __ldg(bout))));
}

// ---------------------------------------------------------------------------
extern "C" void kernel_launch(void* const* d_in, const int* in_sizes, int n_in,
                              void* d_out, int out_size) {
    const float* x    = (const float*)d_in[0];
    const int*   ei   = (const int*)d_in[1];
    const float* W1   = (const float*)d_in[2];
    const float* b1   = (const float*)d_in[3];
    const float* W2   = (const float*)d_in[4];
    const float* b2   = (const float*)d_in[5];
    const float* W3   = (const float*)d_in[6];
    const float* b3   = (const float*)d_in[7];
    const float* Ws02 = (const float*)d_in[8];
    const float* bs02 = (const float*)d_in[9];
    const float* Ws03 = (const float*)d_in[10];
    const float* bs03 = (const float*)d_in[11];
    const float* Ws13 = (const float*)d_in[12];
    const float* bs13 = (const float*)d_in[13];
    const float* Wout = (const float*)d_in[14];
    const float* bout = (const float*)d_in[15];

    int N = in_sizes[0] / 256;
    int E = in_sizes[1] / 2;
    const int* esrc = ei;
    const int* edst = ei + E;
    float* out = (float*)d_out;

    float *p_h1, *p_s02, *p_s03, *p_x1, *p_h2, *p_s13, *p_x2, *p_h3;
    cudaGetSymbolAddress((void**)&p_h1, g_h1);
    cudaGetSymbolAddress((void**)&p_s02, g_s02);
    cudaGetSymbolAddress((void**)&p_s03, g_s03);
    cudaGetSymbolAddress((void**)&p_x1, g_x1);
    cudaGetSymbolAddress((void**)&p_h2, g_h2);
    cudaGetSymbolAddress((void**)&p_s13, g_s13);
    cudaGetSymbolAddress((void**)&p_x2, g_x2);
    cudaGetSymbolAddress((void**)&p_h3, g_h3);

    // graph structure (rebuilt every launch; same edge data -> same structure)
    k_zero<<<(N + 255) / 256, 256>>>(N);
    k_hist<<<(E + 255) / 256, 256>>>(edst, E);
    k_scan<<<1, 1024>>>(N, (N + 1023) / 1024);
    k_scatter<<<(E + 255) / 256, 256>>>(esrc, edst, E);

    int gemm_blocks = (N + 63) / 64;
    int agg_blocks = (N + 7) / 8;

    // layer 1 + skip projections off x (single pass over x)
    k_gemm<256, 7, 4, 6><<<gemm_blocks, 256>>>(x, N, W1, Ws02, Ws03,
                                               p_h1, p_s02, p_s03);
    k_agg1<<<agg_blocks, 256>>>(b1, N);

    // layer 2 + 1->3 skip projection off x1
    k_gemm<64, 3, 2, 3><<<gemm_blocks, 256>>>(p_x1, N, W2, Ws13, nullptr,
                                              p_h2, p_s13, nullptr);
    k_agg2<<<agg_blocks, 256>>>(b2, bs02, N);

    // layer 3
    k_gemm<32, 1, 1, 1><<<gemm_blocks, 256>>>(p_x2, N, W3, nullptr, nullptr,
                                              p_h3, nullptr, nullptr);
    k_agg3<<<agg_blocks, 256>>>(b3, bs03, bs13, Wout, bout, out, N);
}